// round 9
// baseline (speedup 1.0000x reference)
#include <cuda_runtime.h>
#include <cstdint>
#include <cstddef>

#define KDIM 512
#define NRE 257
#define NTOT 514
#define NPAD 576
#define BM 256
#define BN 96
#define BK 32
#define STAGES 2
#define THREADS 256
#define A_STAGE_BYTES (BM * BK * 4)                 // 32768
#define B_STAGE_BYTES (BN * BK * 4)                 // 12288
#define STAGE_BYTES (A_STAGE_BYTES + B_STAGE_BYTES) // 45056
#define SMEM_BYTES (STAGES * STAGE_BYTES)           // 90112
#define B_OFF32 (A_STAGE_BYTES / 4)                 // 8192
#define STG_STRIDE 100

// Pre-converted, zero-padded, k-pair-permuted B (tf32 bits).
// Row n, k8 group: element order [k0,k4,k1,k5,k2,k6,k3,k7] so (t, t+4) is 8B-contiguous.
__device__ uint32_t g_Bcvt[NPAD * KDIM];

__device__ __forceinline__ void mma_tf32(float& c0, float& c1, float& c2, float& c3,
                                         uint32_t a0, uint32_t a1, uint32_t a2, uint32_t a3,
                                         uint32_t b0, uint32_t b1) {
    asm volatile(
        "mma.sync.aligned.m16n8k8.row.col.f32.tf32.tf32.f32 "
        "{%0,%1,%2,%3}, {%4,%5,%6,%7}, {%8,%9}, {%0,%1,%2,%3};\n"
        : "+f"(c0), "+f"(c1), "+f"(c2), "+f"(c3)
        : "r"(a0), "r"(a1), "r"(a2), "r"(a3), "r"(b0), "r"(b1));
}

__device__ __forceinline__ uint32_t f2tf32(float f) {
    uint32_t r;
    asm volatile("cvt.rna.tf32.f32 %0, %1;\n" : "=r"(r) : "f"(f));
    return r;
}

__device__ __forceinline__ uint32_t f2tf32_u(uint32_t fbits) {
    uint32_t r;
    asm volatile("cvt.rna.tf32.f32 %0, %1;\n" : "=r"(r) : "r"(fbits));
    return r;
}

__device__ __forceinline__ void cpa16(uint32_t dst, const void* src) {
    asm volatile("cp.async.cg.shared.global [%0], [%1], 16;" :: "r"(dst), "l"(src));
}

template <int N>
__device__ __forceinline__ void cpa_wait() {
    asm volatile("cp.async.wait_group %0;" :: "n"(N) : "memory");
}

// ---- pre-kernel: padded, permuted tf32 B ----
__global__ void build_B_kernel(const float* __restrict__ MR, const float* __restrict__ MI) {
    int idx = blockIdx.x * blockDim.x + threadIdx.x;   // 0 .. NPAD*KDIM-1
    int n = idx >> 9;
    int k = idx & 511;
    float v = 0.f;
    if (n < NRE)       v = MR[(size_t)n * KDIM + k];
    else if (n < NTOT) v = MI[(size_t)(n - NRE) * KDIM + k];
    int p = (k & ~7) | (((k & 3) << 1) | ((k >> 2) & 1));   // pair-permute within k8 group
    g_Bcvt[(size_t)n * KDIM + p] = f2tf32(v);
}

// Cooperative stage load: A 256x32 raw fp32 + B 96x32 pre-converted.
__device__ __forceinline__ void load_stage(const float* __restrict__ X, uint32_t smem_u32,
                                           int m0, int n0, int tid, int kt, int stage) {
    const uint32_t abase = smem_u32 + stage * STAGE_BYTES;
    // A: 256 rows x 32 fp32, 16B-chunk swizzle ch ^ (row&7)
#pragma unroll
    for (int i = 0; i < 8; i++) {
        int idx = tid + i * THREADS;      // 0..2047
        int row = idx >> 3;               // 0..255
        int ch  = idx & 7;
        uint32_t dst = abase + row * 128 + ((ch * 16) ^ ((row & 7) * 16));
        cpa16(dst, X + (size_t)(m0 + row) * KDIM + kt * BK + ch * 4);
    }
    // B: 96 rows x 32 tf32 (pre-permuted), 32B-window rotation by row for LDS.64
    const uint32_t bbase = abase + A_STAGE_BYTES;
#pragma unroll
    for (int i = 0; i < 3; i++) {
        int idx = tid + i * THREADS;      // 0..767
        int row = idx >> 3;               // 0..95
        int ch  = idx & 7;
        int win = ch >> 1, half = ch & 1;
        uint32_t dst = bbase + row * 128 + (((win + row) & 3) << 5) + (half << 4);
        cpa16(dst, g_Bcvt + (size_t)(n0 + row) * KDIM + kt * BK + ch * 4);
    }
    asm volatile("cp.async.commit_group;" ::: "memory");
}

__global__ void __launch_bounds__(THREADS, 2)
rfft_wmma_kernel(const float* __restrict__ X, float* __restrict__ OUT, int M) {
    extern __shared__ __align__(1024) char smem[];
    uint32_t* Ssm = (uint32_t*)smem;

    const int tid = threadIdx.x;
    const int w = tid >> 5;
    const int lane = tid & 31;
    const int wm = w >> 1;            // 0..3 : 64-row M slice
    const int wn = w & 1;             // 0..1 : 48-col N slice
    const int g = lane >> 2;          // 0..7
    const int t = lane & 3;           // 0..3
    const int m0 = blockIdx.y * BM;
    const int n0 = blockIdx.x * BN;
    const uint32_t smem_u32 = (uint32_t)__cvta_generic_to_shared(smem);

#pragma unroll
    for (int p = 0; p < STAGES; p++)
        load_stage(X, smem_u32, m0, n0, tid, p, p);

    float acc[4][6][4];
#pragma unroll
    for (int mb = 0; mb < 4; mb++)
#pragma unroll
        for (int nb = 0; nb < 6; nb++)
#pragma unroll
            for (int j = 0; j < 4; j++)
                acc[mb][nb][j] = 0.f;

    const int gsw = g << 2;
    const int aBase = (wm * 64 + g) * 32;                       // + mb*512 immediate
    const int bBase = B_OFF32 + (wn * 48 + g) * 32 + t * 2;     // + nb*256 immediate
    const int rot = g & 3;                                      // n&3 == g&3 for all nb

#pragma unroll 1
    for (int kt = 0; kt < KDIM / BK; kt++) {
        if (kt < 15) cpa_wait<1>();
        else         cpa_wait<0>();
        __syncthreads();

        const uint32_t* sp = Ssm + (kt & 1) * (STAGE_BYTES / 4);
#pragma unroll
        for (int ks = 0; ks < 4; ks++) {
            const int kb = ks * 8;
            const int c0 = (kb + t) ^ gsw;
            const int c1 = c0 ^ 4;
            const int woff = ((ks + rot) & 3) << 3;
            uint32_t b[6][2];
#pragma unroll
            for (int nb = 0; nb < 6; nb++) {
                uint2 v = *(const uint2*)(sp + bBase + nb * 256 + woff);
                b[nb][0] = v.x;
                b[nb][1] = v.y;
            }
#pragma unroll
            for (int mb = 0; mb < 4; mb++) {
                const uint32_t* ap = sp + aBase + mb * 512;
                uint32_t a0 = f2tf32_u(ap[c0]);
                uint32_t a1 = f2tf32_u(ap[c0 + 256]);   // row + 8
                uint32_t a2 = f2tf32_u(ap[c1]);
                uint32_t a3 = f2tf32_u(ap[c1 + 256]);
#pragma unroll
                for (int nb = 0; nb < 6; nb++)
                    mma_tf32(acc[mb][nb][0], acc[mb][nb][1], acc[mb][nb][2], acc[mb][nb][3],
                             a0, a1, a2, a3, b[nb][0], b[nb][1]);
            }
        }

        __syncthreads();
        if (kt + STAGES < KDIM / BK)
            load_stage(X, smem_u32, m0, n0, tid, kt + STAGES, kt & 1);
    }

    // ---- epilogue: two 128-row halves, smem-staged, coalesced stores ----
    __syncthreads();
    float* stg = (float*)smem;     // 128 x STG_STRIDE floats = 51.2 KB < 88 KB
    float* re = OUT;
    float* im = OUT + (size_t)M * NRE;
#pragma unroll 1
    for (int h = 0; h < 2; h++) {
        if ((wm >> 1) == h) {
#pragma unroll
            for (int mb = 0; mb < 4; mb++) {
#pragma unroll
                for (int nb = 0; nb < 6; nb++) {
                    const int row = (wm & 1) * 64 + mb * 16 + g;
                    const int col = wn * 48 + nb * 8 + 2 * t;
                    stg[row * STG_STRIDE + col]           = acc[mb][nb][0];
                    stg[row * STG_STRIDE + col + 1]       = acc[mb][nb][1];
                    stg[(row + 8) * STG_STRIDE + col]     = acc[mb][nb][2];
                    stg[(row + 8) * STG_STRIDE + col + 1] = acc[mb][nb][3];
                }
            }
        }
        __syncthreads();
#pragma unroll
        for (int rr = 0; rr < 16; rr++) {
            const int row = w * 16 + rr;          // 0..127
            const size_t r = m0 + h * 128 + row;
#pragma unroll
            for (int c = 0; c < 3; c++) {
                const int n = n0 + c * 32 + lane;
                const float v = stg[row * STG_STRIDE + c * 32 + lane];
                if (n < NRE)       re[r * NRE + n] = v;
                else if (n < NTOT) im[r * NRE + (n - NRE)] = v;
            }
        }
        __syncthreads();
    }
}

extern "C" void kernel_launch(void* const* d_in, const int* in_sizes, int n_in,
                              void* d_out, int out_size) {
    const float* X  = (const float*)d_in[0];
    const float* MR = (const float*)d_in[1];
    const float* MI = (const float*)d_in[2];
    float* OUT = (float*)d_out;
    const int M = in_sizes[0] / KDIM;   // 128000

    build_B_kernel<<<(NPAD * KDIM) / 256, 256>>>(MR, MI);

    cudaFuncSetAttribute(rfft_wmma_kernel, cudaFuncAttributeMaxDynamicSharedMemorySize, SMEM_BYTES);
    dim3 grid(NPAD / BN, M / BM);   // (6, 500)
    rfft_wmma_kernel<<<grid, THREADS, SMEM_BYTES>>>(X, OUT, M);
}